// round 12
// baseline (speedup 1.0000x reference)
#include <cuda_runtime.h>

// PointPillars pseudo-image: fused (init+scatter) prologue + EXACT R3 gather.
// Output: (B=16, C=64, NY=400, NX=400) float32 = 655 MB, fully written each call.

#define B_   16
#define C_   64
#define NY_  400
#define NX_  400
#define PLANE  (NY_ * NX_)      // 160,000 pixels per frame
#define NPIX   (B_ * PLANE)     // 2,560,000 total pixels

#define PRO_BLOCKS  148         // <= SM count; tiny kernel => all co-resident
#define PRO_THREADS 256

// pixel -> (local voxel index + 1), 0 = empty. 5.12 MB __device__ scratch.
__device__ unsigned short g_map[NPIX];

// spin-barrier counters; self-reset at the end of every call (stateless across calls)
__device__ unsigned int g_arrive = 0;
__device__ unsigned int g_depart = 0;

// ---------------------------------------------------------------------------
// 1) fused prologue: zero the map, device-wide barrier, scatter voxel ids.
//    All PRO_BLOCKS are guaranteed co-resident (tiny kernel), so the spin
//    barrier cannot deadlock. Counters are restored to 0 by the last block.
// ---------------------------------------------------------------------------
__global__ void __launch_bounds__(PRO_THREADS) prologue_kernel(
    const int* __restrict__ idx, int n, int nvb)
{
    const int tid = blockIdx.x * blockDim.x + threadIdx.x;
    const int nth = gridDim.x * blockDim.x;

    // ---- phase 1: map = 0 (int4 stores: 8 u16 entries each) ----
    for (int i = tid; i < NPIX / 8; i += nth) {
        reinterpret_cast<int4*>(g_map)[i] = make_int4(0, 0, 0, 0);
    }
    __threadfence();            // make zeros visible before arrival
    __syncthreads();

    // ---- device-wide barrier (arrive + spin), one thread per block ----
    if (threadIdx.x == 0) {
        atomicAdd(&g_arrive, 1u);
        while (atomicAdd(&g_arrive, 0u) < (unsigned)gridDim.x) { }
        __threadfence();        // acquire: order phase-2 stores after observed zeros
    }
    __syncthreads();

    // ---- phase 2: scatter local voxel ids (+1); unique cells, no races ----
    for (int i = tid; i < n; i += nth) {
        int4 v = reinterpret_cast<const int4*>(idx)[i];     // (b, z, y, x)
        int local = i - v.x * nvb;                          // index within batch
        g_map[v.x * PLANE + v.z * NX_ + v.w] = (unsigned short)(local + 1);
    }
    __syncthreads();

    // ---- reset counters: last departing block restores pristine state ----
    if (threadIdx.x == 0) {
        unsigned d = atomicAdd(&g_depart, 1u);
        if (d == (unsigned)gridDim.x - 1u) {
            atomicExch(&g_arrive, 0u);
            atomicExch(&g_depart, 0u);
        }
    }
}

// ---------------------------------------------------------------------------
// 2) gather: EXACT R3 body and launch shape (proven local optimum).
//    One thread per quad of 4 consecutive x-pixels, 64 channels in chunks
//    of 4; predicated feature loads, 512B-coalesced warp stores per channel.
// ---------------------------------------------------------------------------
__global__ void __launch_bounds__(256) gather_kernel(
    const float* __restrict__ feat, float* __restrict__ out, int nvb)
{
    int q = blockIdx.x * blockDim.x + threadIdx.x;   // quad id
    if (q >= NPIX / 4) return;

    int p   = q * 4;                                 // flat pixel index
    int b   = p / PLANE;
    int rem = p - b * PLANE;                         // quad-aligned offset in plane

    ushort4 mv = *reinterpret_cast<const ushort4*>(g_map + p);
    int m0 = (int)mv.x, m1 = (int)mv.y, m2 = (int)mv.z, m3 = (int)mv.w;

    long long base = (long long)b * nvb - 1;         // row = base + m (when m>0)
    const float* f0 = feat + (base + m0) * C_;
    const float* f1 = feat + (base + m1) * C_;
    const float* f2 = feat + (base + m2) * C_;
    const float* f3 = feat + (base + m3) * C_;

    float* obase = out + (long long)b * C_ * PLANE + rem;
    const float4 zero = make_float4(0.f, 0.f, 0.f, 0.f);

#pragma unroll 4
    for (int c = 0; c < C_; c += 4) {
        float4 a0 = (m0 > 0) ? *reinterpret_cast<const float4*>(f0 + c) : zero;
        float4 a1 = (m1 > 0) ? *reinterpret_cast<const float4*>(f1 + c) : zero;
        float4 a2 = (m2 > 0) ? *reinterpret_cast<const float4*>(f2 + c) : zero;
        float4 a3 = (m3 > 0) ? *reinterpret_cast<const float4*>(f3 + c) : zero;

        float4 o;
        o.x = a0.x; o.y = a1.x; o.z = a2.x; o.w = a3.x;
        *reinterpret_cast<float4*>(obase + (long long)(c + 0) * PLANE) = o;
        o.x = a0.y; o.y = a1.y; o.z = a2.y; o.w = a3.y;
        *reinterpret_cast<float4*>(obase + (long long)(c + 1) * PLANE) = o;
        o.x = a0.z; o.y = a1.z; o.z = a2.z; o.w = a3.z;
        *reinterpret_cast<float4*>(obase + (long long)(c + 2) * PLANE) = o;
        o.x = a0.w; o.y = a1.w; o.z = a2.w; o.w = a3.w;
        *reinterpret_cast<float4*>(obase + (long long)(c + 3) * PLANE) = o;
    }
}

// ---------------------------------------------------------------------------
// launch: fused prologue -> gather (two nodes instead of three)
// ---------------------------------------------------------------------------
extern "C" void kernel_launch(void* const* d_in, const int* in_sizes, int n_in,
                              void* d_out, int out_size) {
    const float* feat = (const float*)d_in[0];      // (N, 64) float32
    const int*   idx  = (const int*)d_in[1];        // (N, 4)  int32
    float*       out  = (float*)d_out;              // (16, 64, 400, 400)

    int n_vox = in_sizes[1] / 4;
    int nvb   = n_vox / B_;                         // voxels per batch frame

    prologue_kernel<<<PRO_BLOCKS, PRO_THREADS>>>(idx, n_vox, nvb);
    gather_kernel<<<(NPIX / 4 + 255) / 256, 256>>>(feat, out, nvb);
}

// round 13
// speedup vs baseline: 1.0306x; 1.0306x over previous
#include <cuda_runtime.h>

// PointPillars pseudo-image: inverse-map (u16) + coalesced gather.
// Structure = R3 (best known: 119.2us), with PDL (programmatic dependent
// launch) edges so each kernel's launch ramp overlaps its predecessor's
// execution. Kernel bodies are otherwise byte-identical to R3.
// Output: (B=16, C=64, NY=400, NX=400) float32 = 655 MB, fully written.

#define B_   16
#define C_   64
#define NY_  400
#define NX_  400
#define PLANE  (NY_ * NX_)      // 160,000 pixels per frame
#define NPIX   (B_ * PLANE)     // 2,560,000 total pixels

// pixel -> (local voxel index + 1), 0 = empty. 5.12 MB __device__ scratch.
__device__ unsigned short g_map[NPIX];

// ---------------------------------------------------------------------------
// 1) init map to 0 (int4 stores: 8 u16 entries each). Trigger early so the
//    dependent scatter grid can begin ramping while init runs.
// ---------------------------------------------------------------------------
__global__ void init_map_kernel() {
    cudaTriggerProgrammaticLaunchCompletion();
    int i = blockIdx.x * blockDim.x + threadIdx.x;
    if (i < NPIX / 8) {
        reinterpret_cast<int4*>(g_map)[i] = make_int4(0, 0, 0, 0);
    }
}

// ---------------------------------------------------------------------------
// 2) scatter: launched with programmatic serialization. Loads idx BEFORE the
//    dependency sync (independent of the map), then waits for init's stores
//    to be visible, then writes the map. Unique cells -> no races.
// ---------------------------------------------------------------------------
__global__ void scatter_map_kernel(const int* __restrict__ idx, int n, int nvb) {
    cudaTriggerProgrammaticLaunchCompletion();   // let gather ramp early too
    int i = blockIdx.x * blockDim.x + threadIdx.x;

    int4 v = make_int4(0, 0, 0, 0);
    if (i < n) v = reinterpret_cast<const int4*>(idx)[i];   // overlapped load

    cudaGridDependencySynchronize();             // init's zeros now visible

    if (i < n) {
        int local = i - v.x * nvb;                          // index within batch
        g_map[v.x * PLANE + v.z * NX_ + v.w] = (unsigned short)(local + 1);
    }
}

// ---------------------------------------------------------------------------
// 3) gather: EXACT R3 body; only addition is the dependency sync immediately
//    before the map read (address math beforehand is map-independent).
// ---------------------------------------------------------------------------
__global__ void __launch_bounds__(256) gather_kernel(
    const float* __restrict__ feat, float* __restrict__ out, int nvb)
{
    int q = blockIdx.x * blockDim.x + threadIdx.x;   // quad id

    int p   = q * 4;                                 // flat pixel index
    int b   = p / PLANE;
    int rem = p - b * PLANE;                         // quad-aligned offset in plane

    cudaGridDependencySynchronize();                 // scatter complete

    if (q >= NPIX / 4) return;

    ushort4 mv = *reinterpret_cast<const ushort4*>(g_map + p);
    int m0 = (int)mv.x, m1 = (int)mv.y, m2 = (int)mv.z, m3 = (int)mv.w;

    long long base = (long long)b * nvb - 1;         // row = base + m (when m>0)
    const float* f0 = feat + (base + m0) * C_;
    const float* f1 = feat + (base + m1) * C_;
    const float* f2 = feat + (base + m2) * C_;
    const float* f3 = feat + (base + m3) * C_;

    float* obase = out + (long long)b * C_ * PLANE + rem;
    const float4 zero = make_float4(0.f, 0.f, 0.f, 0.f);

#pragma unroll 4
    for (int c = 0; c < C_; c += 4) {
        float4 a0 = (m0 > 0) ? *reinterpret_cast<const float4*>(f0 + c) : zero;
        float4 a1 = (m1 > 0) ? *reinterpret_cast<const float4*>(f1 + c) : zero;
        float4 a2 = (m2 > 0) ? *reinterpret_cast<const float4*>(f2 + c) : zero;
        float4 a3 = (m3 > 0) ? *reinterpret_cast<const float4*>(f3 + c) : zero;

        float4 o;
        o.x = a0.x; o.y = a1.x; o.z = a2.x; o.w = a3.x;
        *reinterpret_cast<float4*>(obase + (long long)(c + 0) * PLANE) = o;
        o.x = a0.y; o.y = a1.y; o.z = a2.y; o.w = a3.y;
        *reinterpret_cast<float4*>(obase + (long long)(c + 1) * PLANE) = o;
        o.x = a0.z; o.y = a1.z; o.z = a2.z; o.w = a3.z;
        *reinterpret_cast<float4*>(obase + (long long)(c + 2) * PLANE) = o;
        o.x = a0.w; o.y = a1.w; o.z = a2.w; o.w = a3.w;
        *reinterpret_cast<float4*>(obase + (long long)(c + 3) * PLANE) = o;
    }
}

// ---------------------------------------------------------------------------
// launch: init -> scatter -> gather with programmatic (PDL) edges
// ---------------------------------------------------------------------------
extern "C" void kernel_launch(void* const* d_in, const int* in_sizes, int n_in,
                              void* d_out, int out_size) {
    const float* feat = (const float*)d_in[0];      // (N, 64) float32
    const int*   idx  = (const int*)d_in[1];        // (N, 4)  int32
    float*       out  = (float*)d_out;              // (16, 64, 400, 400)

    int n_vox = in_sizes[1] / 4;
    int nvb   = n_vox / B_;                         // voxels per batch frame

    // node 1: init (plain launch)
    init_map_kernel<<<(NPIX / 8 + 255) / 256, 256>>>();

    cudaLaunchAttribute attr[1];
    attr[0].id = cudaLaunchAttributeProgrammaticStreamSerialization;
    attr[0].val.programmaticStreamSerializationAllowed = 1;

    // node 2: scatter (PDL w.r.t. init)
    {
        cudaLaunchConfig_t cfg = {};
        cfg.gridDim  = dim3((n_vox + 255) / 256);
        cfg.blockDim = dim3(256);
        cfg.attrs    = attr;
        cfg.numAttrs = 1;
        cudaLaunchKernelEx(&cfg, scatter_map_kernel, idx, n_vox, nvb);
    }

    // node 3: gather (PDL w.r.t. scatter)
    {
        cudaLaunchConfig_t cfg = {};
        cfg.gridDim  = dim3((NPIX / 4 + 255) / 256);
        cfg.blockDim = dim3(256);
        cfg.attrs    = attr;
        cfg.numAttrs = 1;
        cudaLaunchKernelEx(&cfg, gather_kernel, feat, out, nvb);
    }
}